// round 8
// baseline (speedup 1.0000x reference)
#include <cuda_runtime.h>
#include <math.h>
#include <float.h>

#define Bb   512
#define Cc   2048
#define HWn  48
#define NAT  51
#define HIDn 128
#define S1   16    // K-splits for pooled @ W1^T  (K=2048 -> 128/split)
#define NTIL 32    // channel tiles in gate kernel (2048/64)

// Scratch (static __device__ globals: allocation-free rule)
__device__ float g_pooled[Bb * Cc];            // max_hw(body*A*face), 0 for non-front rows
__device__ float g_bmean [Bb * Cc];            // mean_hw(body)
__device__ float g_hp    [S1 * Bb * HIDn];     // split-K partials of pooled @ W1^T
__device__ float g_h     [Bb * HIDn];          // relu(sum hp + b1)
__device__ float g_zp    [NTIL * NAT * Bb];    // per-n-tile partials of gap @ Wl^T, [nt][j][b]

// ---------------------------------------------------------------------------
// K1: streaming pass, float4 loads (unchanged — proven, near HBM bound).
// ---------------------------------------------------------------------------
__global__ void __launch_bounds__(256) k1_reduce(
    const float* __restrict__ body, const float* __restrict__ face,
    const float* __restrict__ Af,   const int*   __restrict__ pose)
{
    __shared__ float sm_s[8][96];
    __shared__ float sm_m[8][96];
    __shared__ float out_s[64], out_m[64];
    int tid  = threadIdx.x;
    int wid  = tid >> 5;
    int lane = tid & 31;
    int blk_ch = blockIdx.x * 64;
    int b = blk_ch >> 11;
    bool front = (pose[b] == 1);
    int wbase = blk_ch + wid * 8;

    const float4* bp4 = (const float4*)body + (size_t)wbase * 12;
    float4 bv[3];
    #pragma unroll
    for (int k = 0; k < 3; k++)
        bv[k] = bp4[k * 32 + lane];
    if (front) {
        const float4* fp4 = (const float4*)face + (size_t)wbase * 12;
        const float4* ap4 = (const float4*)Af   + (size_t)(wbase & (Cc - 1)) * 12;
        #pragma unroll
        for (int k = 0; k < 3; k++) {
            float4 fv = fp4[k * 32 + lane];
            float4 av = ap4[k * 32 + lane];
            float m01 = fmaxf(bv[k].x * av.x * fv.x, bv[k].y * av.y * fv.y);
            float m23 = fmaxf(bv[k].z * av.z * fv.z, bv[k].w * av.w * fv.w);
            sm_m[wid][k * 32 + lane] = fmaxf(m01, m23);
        }
    }
    #pragma unroll
    for (int k = 0; k < 3; k++)
        sm_s[wid][k * 32 + lane] = (bv[k].x + bv[k].y) + (bv[k].z + bv[k].w);
    __syncthreads();

    {
        int chl = tid >> 2;
        int w2  = chl >> 3;
        int off = (chl & 7) * 12 + (tid & 3) * 3;
        float ss = sm_s[w2][off] + sm_s[w2][off + 1] + sm_s[w2][off + 2];
        ss += __shfl_xor_sync(0xffffffffu, ss, 1);
        ss += __shfl_xor_sync(0xffffffffu, ss, 2);
        float mm = 0.f;
        if (front) {
            mm = fmaxf(fmaxf(sm_m[w2][off], sm_m[w2][off + 1]), sm_m[w2][off + 2]);
            mm = fmaxf(mm, __shfl_xor_sync(0xffffffffu, mm, 1));
            mm = fmaxf(mm, __shfl_xor_sync(0xffffffffu, mm, 2));
        }
        if ((tid & 3) == 0) {
            out_s[chl] = ss * (1.0f / 48.0f);
            out_m[chl] = mm;
        }
    }
    __syncthreads();
    if (tid < 64)        g_bmean [blk_ch + tid]      = out_s[tid];
    else if (tid < 128)  g_pooled[blk_ch + tid - 64] = out_m[tid - 64];
}

// ---------------------------------------------------------------------------
// GEMM1 split-K: hp[s] = pooled[512, k-chunk] @ W1[128, k-chunk]^T (unchanged)
// ---------------------------------------------------------------------------
__global__ void __launch_bounds__(256) gemm1(
    const float* __restrict__ A, const float* __restrict__ Bw,
    float* __restrict__ hp)
{
    __shared__ float As[16][68];
    __shared__ float Bs[16][68];
    int s  = blockIdx.z;
    int m0 = blockIdx.x * 64;
    int n0 = blockIdx.y * 64;
    int k0 = s * (Cc / S1);
    int tid = threadIdx.x;
    int tx = tid & 15, ty = tid >> 4;
    int r  = tid >> 2;
    int q  = (tid & 3) * 4;
    float acc[4][4] = {};

    const float* ap = &A [(size_t)(m0 + r) * Cc + k0 + q];
    const float* bp = &Bw[(size_t)(n0 + r) * Cc + k0 + q];
    float4 areg = *(const float4*)ap;
    float4 breg = *(const float4*)bp;

    #pragma unroll
    for (int kt = 0; kt < Cc / S1; kt += 16) {
        As[q+0][r] = areg.x; As[q+1][r] = areg.y; As[q+2][r] = areg.z; As[q+3][r] = areg.w;
        Bs[q+0][r] = breg.x; Bs[q+1][r] = breg.y; Bs[q+2][r] = breg.z; Bs[q+3][r] = breg.w;
        __syncthreads();
        if (kt + 16 < Cc / S1) {
            areg = *(const float4*)(ap + kt + 16);
            breg = *(const float4*)(bp + kt + 16);
        }
        #pragma unroll
        for (int kk = 0; kk < 16; kk++) {
            float4 a4 = *(const float4*)&As[kk][ty * 4];
            float4 b4 = *(const float4*)&Bs[kk][tx * 4];
            float a[4]  = {a4.x, a4.y, a4.z, a4.w};
            float bb[4] = {b4.x, b4.y, b4.z, b4.w};
            #pragma unroll
            for (int i = 0; i < 4; i++)
                #pragma unroll
                for (int j = 0; j < 4; j++)
                    acc[i][j] = fmaf(a[i], bb[j], acc[i][j]);
        }
        __syncthreads();
    }
    #pragma unroll
    for (int i = 0; i < 4; i++) {
        int m = m0 + ty * 4 + i;
        #pragma unroll
        for (int j = 0; j < 4; j++) {
            int n = n0 + tx * 4 + j;
            hp[((size_t)s * Bb + m) * HIDn + n] = acc[i][j];
        }
    }
}

// ---------------------------------------------------------------------------
// hreduce: h = relu(sum_s hp[s] + b1)  (unchanged)
// ---------------------------------------------------------------------------
__global__ void __launch_bounds__(256) hreduce(const float* __restrict__ b1v)
{
    int i4 = blockIdx.x * 256 + threadIdx.x;
    float4 v = *(const float4*)&g_hp[(size_t)i4 * 4];
    #pragma unroll
    for (int s = 1; s < S1; s++) {
        float4 t = *(const float4*)&g_hp[(size_t)s * (Bb * HIDn) + (size_t)i4 * 4];
        v.x += t.x; v.y += t.y; v.z += t.z; v.w += t.w;
    }
    float4 bv = *(const float4*)&b1v[(i4 & 31) * 4];
    v.x = fmaxf(v.x + bv.x, 0.f);
    v.y = fmaxf(v.y + bv.y, 0.f);
    v.z = fmaxf(v.z + bv.z, 0.f);
    v.w = fmaxf(v.w + bv.w, 0.f);
    *(float4*)&g_h[(size_t)i4 * 4] = v;
}

// ---------------------------------------------------------------------------
// GATE v5: same 32(m)x64(n) tile + full-K smem + 1 barrier as v4, but
// 256 THREADS with a 2x4 micro-tile. Same smem (53 KB, 4 blocks/SM) but
// 8 warps/block -> 32 resident warps/SM (50% occ) for latency hiding.
// ---------------------------------------------------------------------------
__global__ void __launch_bounds__(256) gemm_gate(
    const float* __restrict__ W2,  const float* __restrict__ b2v,
    const float* __restrict__ Wl,  const int*   __restrict__ pose)
{
    __shared__ __align__(16) float smemBuf[128 * 36 + 128 * 68];   // 53248 B
    float (*As)[36]   = (float(*)[36]) smemBuf;                    // [128][36]
    float (*Bs)[68]   = (float(*)[68])(smemBuf + 128 * 36);        // [128][68]
    float (*gapT)[36] = (float(*)[36]) smemBuf;                    // [64][36]
    float (*WlT)[68]  = (float(*)[68])(smemBuf + 128 * 36);        // [64][68]

    int m0 = blockIdx.x * 32;
    int n0 = blockIdx.y * 64;
    int tid = threadIdx.x;
    int tx = tid & 15;            // n: 4 cols each
    int ty = tid >> 4;            // 0..15, m: 2 rows each
    float acc[2][4] = {};

    // ---- load phase: entire K=128 for A (32 rows) and B (64 rows) ----
    {
        int ra = tid >> 3;                  // 0..31
        int qa = (tid & 7) * 4;             // 0..28
        const float* ap = &g_h[(size_t)(m0 + ra) * HIDn + qa];
        #pragma unroll
        for (int kc = 0; kc < HIDn; kc += 32) {
            float4 v = *(const float4*)(ap + kc);
            As[kc + qa + 0][ra] = v.x;
            As[kc + qa + 1][ra] = v.y;
            As[kc + qa + 2][ra] = v.z;
            As[kc + qa + 3][ra] = v.w;
        }
        int rb = tid >> 2;                  // 0..63
        int qb = (tid & 3) * 4;             // 0,4,8,12
        const float* bp = &W2[(size_t)(n0 + rb) * HIDn + qb];
        #pragma unroll
        for (int kc = 0; kc < HIDn; kc += 16) {
            float4 v = *(const float4*)(bp + kc);
            Bs[kc + qb + 0][rb] = v.x;
            Bs[kc + qb + 1][rb] = v.y;
            Bs[kc + qb + 2][rb] = v.z;
            Bs[kc + qb + 3][rb] = v.w;
        }
    }
    __syncthreads();

    // ---- compute: 128 kk iterations, zero barriers ----
    #pragma unroll 8
    for (int kk = 0; kk < HIDn; kk++) {
        float2 a2 = *(const float2*)&As[kk][ty * 2];
        float4 b4 = *(const float4*)&Bs[kk][tx * 4];
        float a[2]  = {a2.x, a2.y};
        float bb[4] = {b4.x, b4.y, b4.z, b4.w};
        #pragma unroll
        for (int i = 0; i < 2; i++)
            #pragma unroll
            for (int j = 0; j < 4; j++)
                acc[i][j] = fmaf(a[i], bb[j], acc[i][j]);
    }
    __syncthreads();    // smem free for epilogue overlay

    // ---- epilogue: gap -> gapT, Wl -> WlT, mini-GEMM -> zp ----
    #pragma unroll
    for (int i = 0; i < 2; i++) {
        int m = m0 + ty * 2 + i;
        float fr = (pose[m] == 1) ? 1.0f : 0.0f;
        #pragma unroll
        for (int j = 0; j < 4; j++) {
            int n = n0 + tx * 4 + j;
            float v = acc[i][j] + b2v[n];
            float g = 1.0f / (1.0f + expf(-v));
            gapT[tx * 4 + j][ty * 2 + i] =
                g_bmean[(size_t)m * Cc + n] + fr * g;
        }
    }
    for (int idx = tid; idx < 64 * 68; idx += 256) {
        int cc = idx / 68, j = idx - cc * 68;
        WlT[cc][j] = (j < NAT) ? Wl[(size_t)j * Cc + n0 + cc] : 0.f;
    }
    __syncthreads();

    float acc2[2][4] = {};
    #pragma unroll 8
    for (int cc = 0; cc < 64; cc++) {
        float2 g2 = *(const float2*)&gapT[cc][ty * 2];
        float4 w4 = *(const float4*)&WlT [cc][tx * 4];
        float gg[2] = {g2.x, g2.y};
        float ww[4] = {w4.x, w4.y, w4.z, w4.w};
        #pragma unroll
        for (int i = 0; i < 2; i++)
            #pragma unroll
            for (int j = 0; j < 4; j++)
                acc2[i][j] = fmaf(gg[i], ww[j], acc2[i][j]);
    }
    int nt = blockIdx.y;
    #pragma unroll
    for (int j = 0; j < 4; j++) {
        int attr = tx * 4 + j;
        if (attr < NAT) {
            #pragma unroll
            for (int i = 0; i < 2; i++) {
                int m = m0 + ty * 2 + i;
                g_zp[((size_t)nt * NAT + attr) * Bb + m] = acc2[i][j];
            }
        }
    }
}

// ---------------------------------------------------------------------------
// BN: one block per attribute (NTIL=32 partials).
// ---------------------------------------------------------------------------
__global__ void __launch_bounds__(256) bn_kernel(
    const float* __restrict__ blv, const float* __restrict__ gam,
    const float* __restrict__ bet, float* __restrict__ out)
{
    __shared__ float zbuf[Bb];
    __shared__ float red[256];
    int j   = blockIdx.x;
    int tid = threadIdx.x;
    float bias = blv[j];
    float lsum = 0.f;
    for (int b = tid; b < Bb; b += 256) {
        float z = bias;
        #pragma unroll
        for (int nt = 0; nt < NTIL; nt++)
            z += g_zp[((size_t)nt * NAT + j) * Bb + b];
        zbuf[b] = z;
        lsum += z;
    }
    red[tid] = lsum;
    __syncthreads();
    for (int off = 128; off; off >>= 1) {
        if (tid < off) red[tid] += red[tid + off];
        __syncthreads();
    }
    float mu = red[0] * (1.0f / Bb);
    __syncthreads();
    float lvar = 0.f;
    for (int b = tid; b < Bb; b += 256) {
        float d = zbuf[b] - mu;
        lvar += d * d;
    }
    red[tid] = lvar;
    __syncthreads();
    for (int off = 128; off; off >>= 1) {
        if (tid < off) red[tid] += red[tid + off];
        __syncthreads();
    }
    float inv = rsqrtf(red[0] * (1.0f / Bb) + 1e-5f);
    float ga = gam[j], be = bet[j];
    for (int b = tid; b < Bb; b += 256)
        out[(size_t)b * NAT + j] = ga * (zbuf[b] - mu) * inv + be;
}

// ---------------------------------------------------------------------------
extern "C" void kernel_launch(void* const* d_in, const int* in_sizes, int n_in,
                              void* d_out, int out_size)
{
    const float* body = (const float*)d_in[0];
    const float* face = (const float*)d_in[1];
    const int*   pose = (const int*)  d_in[2];
    const float* Af   = (const float*)d_in[3];
    const float* W1   = (const float*)d_in[4];
    const float* b1v  = (const float*)d_in[5];
    const float* W2   = (const float*)d_in[6];
    const float* b2v  = (const float*)d_in[7];
    const float* Wl   = (const float*)d_in[8];
    const float* blv  = (const float*)d_in[9];
    const float* gam  = (const float*)d_in[10];
    const float* bet  = (const float*)d_in[11];
    float* out = (float*)d_out;

    float *pooled_p, *hp_p;
    cudaGetSymbolAddress((void**)&pooled_p, g_pooled);
    cudaGetSymbolAddress((void**)&hp_p,     g_hp);

    // 1) streaming reduce: pooled max + body mean
    k1_reduce<<<(Bb * Cc) / 64, 256>>>(body, face, Af, pose);
    // 2) hp[s] = pooled @ W1^T  (16-way split-K partials)
    gemm1<<<dim3(Bb / 64, HIDn / 64, S1), 256>>>(pooled_p, W1, hp_p);
    // 3) h = relu(sum hp + b1)
    hreduce<<<(Bb * HIDn / 4) / 256, 256>>>(b1v);
    // 4) gate GEMM v5 (full-K smem, 256 thr, 2x4 micro) + fused z-partials
    gemm_gate<<<dim3(Bb / 32, NTIL), 256>>>(W2, b2v, Wl, pose);
    // 5) reduce partials + bias + batchnorm
    bn_kernel<<<NAT, 256>>>(blv, gam, bet, out);
}